// round 9
// baseline (speedup 1.0000x reference)
#include <cuda_runtime.h>
#include <cstdint>

// ---------------------------------------------------------------------------
// Problem constants
// ---------------------------------------------------------------------------
#define SNN_B   128
#define SNN_T   200
#define SNN_NI  4096
#define SNN_NH  1024
#define SNN_NO  2
#define SNN_M   (SNN_B * SNN_T)          // 25600 GEMM rows

#define PX ((size_t)SNN_M * SNN_NI)      // elems per X plane
#define PW ((size_t)SNN_NH * SNN_NI)     // elems per W plane

// Scratch (static device arrays)
static __device__ __align__(256) int8_t g_Ax[4 * PX];   // 4 x-slice planes, 420MB
static __device__ __align__(256) int8_t g_Ww[4 * PW];   // 4 w-slice planes, 16MB
static __device__ float g_cur1[(size_t)SNN_M * SNN_NH]; // 100MB

// ---------------------------------------------------------------------------
// Helpers (family-generic PTX: ldmatrix sm_75+, int8 mma.sync sm_80+, cp.async)
// ---------------------------------------------------------------------------
__device__ __forceinline__ uint32_t smem_u32(const void* p) {
    uint32_t a;
    asm("{ .reg .u64 t; cvta.to.shared.u64 t, %1; cvt.u32.u64 %0, t; }" : "=r"(a) : "l"(p));
    return a;
}

__device__ __forceinline__ void ldmx4(uint32_t* r, uint32_t addr) {
    asm volatile("ldmatrix.sync.aligned.m8n8.x4.shared.b16 {%0,%1,%2,%3}, [%4];"
                 : "=r"(r[0]), "=r"(r[1]), "=r"(r[2]), "=r"(r[3]) : "r"(addr));
}

__device__ __forceinline__ void mma_s8(int* d, const uint32_t* a,
                                       uint32_t b0, uint32_t b1) {
    asm volatile(
        "mma.sync.aligned.m16n8k32.row.col.s32.s8.s8.s32 "
        "{%0,%1,%2,%3}, {%4,%5,%6,%7}, {%8,%9}, {%0,%1,%2,%3};"
        : "+r"(d[0]), "+r"(d[1]), "+r"(d[2]), "+r"(d[3])
        : "r"(a[0]), "r"(a[1]), "r"(a[2]), "r"(a[3]), "r"(b0), "r"(b1));
}

#define CP_ASYNC16(sd, g) \
    asm volatile("cp.async.cg.shared.global [%0], [%1], 16;" :: "r"(sd), "l"(g))
#define CP_COMMIT()  asm volatile("cp.async.commit_group;" ::: "memory")
#define CP_WAIT(n)   asm volatile("cp.async.wait_group %0;" :: "n"(n) : "memory")

// ---------------------------------------------------------------------------
// Quantization: v*S sliced into 4 signed-7-bit integer slices at 2^-7 steps.
//   v*S = q0 + q1/128 + q2/128^2 + q3/128^3 + e,  |e| <= 0.5*2^-21
// All residual updates are exact in fp32 (Sterbenz). |q0|<=63 needs |v*S|<64.
// ---------------------------------------------------------------------------
__device__ __forceinline__ void quant_store(float4 v, float S, int8_t* base,
                                            size_t plane, size_t idx4) {
    uint32_t pk0 = 0, pk1 = 0, pk2 = 0, pk3 = 0;
    float e[4] = {v.x, v.y, v.z, v.w};
#pragma unroll
    for (int j = 0; j < 4; j++) {
        float v0 = e[j] * S;
        float q0 = rintf(v0);
        float r  = v0 - q0;
        float q1 = rintf(r * 128.f);
        r = fmaf(q1, -0.0078125f, r);
        float q2 = rintf(r * 16384.f);
        r = fmaf(q2, -6.103515625e-05f, r);
        float q3 = rintf(r * 2097152.f);
        pk0 |= ((uint32_t)((int)q0 & 0xFF)) << (8 * j);
        pk1 |= ((uint32_t)((int)q1 & 0xFF)) << (8 * j);
        pk2 |= ((uint32_t)((int)q2 & 0xFF)) << (8 * j);
        pk3 |= ((uint32_t)((int)q3 & 0xFF)) << (8 * j);
    }
    *(uint32_t*)(base + 0 * plane + idx4 * 4) = pk0;
    *(uint32_t*)(base + 1 * plane + idx4 * 4) = pk1;
    *(uint32_t*)(base + 2 * plane + idx4 * 4) = pk2;
    *(uint32_t*)(base + 3 * plane + idx4 * 4) = pk3;
}

__global__ __launch_bounds__(256)
void quantX(const float4* __restrict__ x, int n4) {
    int q = blockIdx.x * 256 + threadIdx.x;
    if (q >= n4) return;
    quant_store(x[q], 4.0f, g_Ax, PX, (size_t)q);      // |x| < 15.9 safe
}

__global__ __launch_bounds__(256)
void quantW(const float4* __restrict__ w, int n4) {
    int q = blockIdx.x * 256 + threadIdx.x;
    if (q >= n4) return;
    quant_store(w[q], 4096.0f, g_Ww, PW, (size_t)q);   // |w| <= 1/64
}

// ---------------------------------------------------------------------------
// fc1 GEMM, exact int8 Ozaki scheme.
//   cur1 = 2^-14 * (C2 + C3/128 + C4/128^2 + C5/128^3) + bias
// where Cc = sum over slice pairs (i,j), i+j+2 == c, of S_ij (exact s32).
// CTA 128(M) x 64(N), 256 threads, 8 warps of 32x32, K-tile 64, cp.async x2.
// ---------------------------------------------------------------------------
#define KT       64
#define NKT      (SNN_NI / KT)          // 64
#define ROWB     80                     // smem bytes per 64-s8 row (16B pad)
#define A_PLANE  (128 * ROWB)           // 10240
#define B_PLANE  (64 * ROWB)            // 5120
#define STAGE    (4 * A_PLANE + 4 * B_PLANE)  // 61440
#define SMEM_BYTES (2 * STAGE)          // 122880

__device__ __forceinline__ void load_tile(int m0, int n0, int kt,
                                          uint32_t sOff, int tid) {
    const int k0 = kt * KT;
#pragma unroll
    for (int i = 0; i < 12; i++) {
        int c = i * 256 + tid;
        if (c < 2048) {                       // A: 4 planes x 128 rows x 4 chunks
            int pl = c >> 9, idx = c & 511, r = idx >> 2, ch = idx & 3;
            const int8_t* g = g_Ax + (size_t)pl * PX
                            + (size_t)(m0 + r) * SNN_NI + k0 + ch * 16;
            uint32_t sd = sOff + pl * A_PLANE + r * ROWB + ch * 16;
            CP_ASYNC16(sd, g);
        } else {                              // B: 4 planes x 64 rows x 4 chunks
            int c2 = c - 2048;
            int pl = c2 >> 8, idx = c2 & 255, r = idx >> 2, ch = idx & 3;
            const int8_t* g = g_Ww + (size_t)pl * PW
                            + (size_t)(n0 + r) * SNN_NI + k0 + ch * 16;
            uint32_t sd = sOff + 4 * A_PLANE + pl * B_PLANE + r * ROWB + ch * 16;
            CP_ASYNC16(sd, g);
        }
    }
    CP_COMMIT();
}

__global__ __launch_bounds__(256, 1)
void fc1_int8(const float* __restrict__ bias) {
    extern __shared__ __align__(128) int8_t smem[];
    const uint32_t sbase = smem_u32(smem);
    const int tid = threadIdx.x;
    const int lid = tid & 31;
    const int wid = tid >> 5;
    const int wy  = wid >> 1;            // 0..3: 32-row band
    const int wx  = wid & 1;             // 0..1: 32-col band
    const int m0  = blockIdx.y * 128;
    const int n0  = blockIdx.x * 64;

    // ldmatrix per-lane address offsets (within a stage)
    uint32_t adrA[4][2], adrB[4][2];
#pragma unroll
    for (int s = 0; s < 4; s++) {
#pragma unroll
        for (int mt = 0; mt < 2; mt++)
            adrA[s][mt] = s * A_PLANE
                + (uint32_t)((wy * 32 + mt * 16 + ((lid >> 3) & 1) * 8 + (lid & 7)) * ROWB)
                + (uint32_t)((lid >> 4) * 16);
#pragma unroll
        for (int pr = 0; pr < 2; pr++)
            adrB[s][pr] = 4 * A_PLANE + s * B_PLANE
                + (uint32_t)((wx * 32 + pr * 16 + (lid >> 4) * 8 + (lid & 7)) * ROWB)
                + (uint32_t)(((lid >> 3) & 1) * 16);
    }

    int acc[4][2][4][4];                 // [class][mt][nt][frag] - all exact s32
#pragma unroll
    for (int c = 0; c < 4; c++)
#pragma unroll
        for (int mt = 0; mt < 2; mt++)
#pragma unroll
            for (int nt = 0; nt < 4; nt++)
#pragma unroll
                for (int j = 0; j < 4; j++) acc[c][mt][nt][j] = 0;

    load_tile(m0, n0, 0, sbase, tid);

    for (int kt = 0; kt < NKT; kt++) {
        const int st = kt & 1;
        if (kt + 1 < NKT) {
            load_tile(m0, n0, kt + 1, sbase + (st ^ 1) * STAGE, tid);
            CP_WAIT(1);
        } else {
            CP_WAIT(0);
        }
        __syncthreads();

        const uint32_t sOff = sbase + st * STAGE;
#pragma unroll
        for (int ks = 0; ks < 2; ks++) {
            const uint32_t kOff = ks * 32;
            uint32_t af[4][2][4], bf[4][2][4];
#pragma unroll
            for (int s = 0; s < 4; s++) {
#pragma unroll
                for (int mt = 0; mt < 2; mt++)
                    ldmx4(af[s][mt], sOff + adrA[s][mt] + kOff);
#pragma unroll
                for (int pr = 0; pr < 2; pr++)
                    ldmx4(bf[s][pr], sOff + adrB[s][pr] + kOff);
            }
#pragma unroll
            for (int mt = 0; mt < 2; mt++)
#pragma unroll
                for (int nt = 0; nt < 4; nt++) {
                    const int pr = nt >> 1, sb = (nt & 1) * 2;
                    // class 2 (i+j=0)
                    mma_s8(acc[0][mt][nt], af[0][mt], bf[0][pr][sb], bf[0][pr][sb + 1]);
                    // class 3 (i+j=1)
                    mma_s8(acc[1][mt][nt], af[0][mt], bf[1][pr][sb], bf[1][pr][sb + 1]);
                    mma_s8(acc[1][mt][nt], af[1][mt], bf[0][pr][sb], bf[0][pr][sb + 1]);
                    // class 4 (i+j=2)
                    mma_s8(acc[2][mt][nt], af[0][mt], bf[2][pr][sb], bf[2][pr][sb + 1]);
                    mma_s8(acc[2][mt][nt], af[1][mt], bf[1][pr][sb], bf[1][pr][sb + 1]);
                    mma_s8(acc[2][mt][nt], af[2][mt], bf[0][pr][sb], bf[0][pr][sb + 1]);
                    // class 5 (i+j=3)
                    mma_s8(acc[3][mt][nt], af[0][mt], bf[3][pr][sb], bf[3][pr][sb + 1]);
                    mma_s8(acc[3][mt][nt], af[1][mt], bf[2][pr][sb], bf[2][pr][sb + 1]);
                    mma_s8(acc[3][mt][nt], af[2][mt], bf[1][pr][sb], bf[1][pr][sb + 1]);
                    mma_s8(acc[3][mt][nt], af[3][mt], bf[0][pr][sb], bf[0][pr][sb + 1]);
                }
        }
        __syncthreads();
    }

    // epilogue: Horner combine of exact class sums, + bias, store fp32
#pragma unroll
    for (int nt = 0; nt < 4; nt++) {
        const int col = n0 + wx * 32 + nt * 8 + (lid & 3) * 2;
        const float b0 = __ldg(bias + col);
        const float b1 = __ldg(bias + col + 1);
#pragma unroll
        for (int mt = 0; mt < 2; mt++) {
            const int row = m0 + wy * 32 + mt * 16 + (lid >> 2);
            float v[4];
#pragma unroll
            for (int j = 0; j < 4; j++) {
                float f = (float)acc[3][mt][nt][j];
                f = fmaf(f, 0.0078125f, (float)acc[2][mt][nt][j]);
                f = fmaf(f, 0.0078125f, (float)acc[1][mt][nt][j]);
                f = fmaf(f, 0.0078125f, (float)acc[0][mt][nt][j]);
                v[j] = f * 6.103515625e-05f;    // 2^-14
            }
            float2 o0 = make_float2(v[0] + b0, v[1] + b1);
            float2 o1 = make_float2(v[2] + b0, v[3] + b1);
            *(float2*)(g_cur1 + (size_t)row * SNN_NH + col)       = o0;
            *(float2*)(g_cur1 + (size_t)(row + 8) * SNN_NH + col) = o1;
        }
    }
}

// ---------------------------------------------------------------------------
// sequential SNN scan (R1-proven, 147us)
// ---------------------------------------------------------------------------
__global__ __launch_bounds__(1024)
void snn_scan(const float* __restrict__ w2, const float* __restrict__ b2,
              float* __restrict__ out_mem, float* __restrict__ out_spk) {
    const int b = blockIdx.x;
    const int h = threadIdx.x;
    const float ALPHA = 0.8187307530779818f;
    const float BETA  = 0.9048374180359595f;

    __shared__ float red0[32];
    __shared__ float red1[32];

    const float w20 = w2[h];
    const float w21 = w2[SNN_NH + h];
    const float b20 = b2[0];
    const float b21 = b2[1];

    float syn1 = 0.f, mem1 = 0.f;
    float syn2a = 0.f, mem2a = 0.f, syn2b = 0.f, mem2b = 0.f;

    const float* cp = g_cur1 + (size_t)b * SNN_T * SNN_NH + h;
    float cur_next = cp[0];

    const int lane = h & 31;
    const int warp = h >> 5;

    for (int t = 0; t < SNN_T; t++) {
        float cur = cur_next;
        if (t + 1 < SNN_T) cur_next = cp[(size_t)(t + 1) * SNN_NH];

        float r1 = (mem1 > 1.0f) ? 1.0f : 0.0f;
        syn1 = fmaf(ALPHA, syn1, cur);
        mem1 = fmaf(BETA, mem1, syn1) - r1;
        float spk = (mem1 > 1.0f) ? 1.0f : 0.0f;

        float v0 = spk * w20;
        float v1 = spk * w21;
#pragma unroll
        for (int off = 16; off > 0; off >>= 1) {
            v0 += __shfl_down_sync(0xffffffffu, v0, off);
            v1 += __shfl_down_sync(0xffffffffu, v1, off);
        }
        if (lane == 0) { red0[warp] = v0; red1[warp] = v1; }
        __syncthreads();

        if (h < 32) {
            float s0 = red0[h];
            float s1 = red1[h];
#pragma unroll
            for (int off = 16; off > 0; off >>= 1) {
                s0 += __shfl_down_sync(0xffffffffu, s0, off);
                s1 += __shfl_down_sync(0xffffffffu, s1, off);
            }
            if (h == 0) {
                float c0 = s0 + b20;
                float c1 = s1 + b21;
                float r2a = (mem2a > 1.0f) ? 1.0f : 0.0f;
                float r2b = (mem2b > 1.0f) ? 1.0f : 0.0f;
                syn2a = fmaf(ALPHA, syn2a, c0);
                syn2b = fmaf(ALPHA, syn2b, c1);
                mem2a = fmaf(BETA, mem2a, syn2a) - r2a;
                mem2b = fmaf(BETA, mem2b, syn2b) - r2b;
                size_t o = ((size_t)b * SNN_T + t) * 2;
                out_mem[o]     = mem2a;
                out_mem[o + 1] = mem2b;
                out_spk[o]     = (mem2a > 1.0f) ? 1.0f : 0.0f;
                out_spk[o + 1] = (mem2b > 1.0f) ? 1.0f : 0.0f;
            }
        }
        __syncthreads();
    }
}

// ---------------------------------------------------------------------------
// Launch
// ---------------------------------------------------------------------------
extern "C" void kernel_launch(void* const* d_in, const int* in_sizes, int n_in,
                              void* d_out, int out_size) {
    const float* x  = (const float*)d_in[0];
    const float* w1 = (const float*)d_in[1];
    const float* b1 = (const float*)d_in[2];
    const float* w2 = (const float*)d_in[3];
    const float* b2 = (const float*)d_in[4];
    float* out = (float*)d_out;
    float* out_mem = out;
    float* out_spk = out + (size_t)SNN_B * SNN_T * SNN_NO;

    cudaFuncSetAttribute(fc1_int8, cudaFuncAttributeMaxDynamicSharedMemorySize,
                         SMEM_BYTES);

    const int nx4 = SNN_M * SNN_NI / 4;    // 26,214,400
    const int nw4 = SNN_NH * SNN_NI / 4;   //  1,048,576... (NH*NI/4)
    quantX<<<(nx4 + 255) / 256, 256>>>((const float4*)x, nx4);
    quantW<<<(nw4 + 255) / 256, 256>>>((const float4*)w1, nw4);

    dim3 grid(SNN_NH / 64, SNN_M / 128);   // (16, 200)
    fc1_int8<<<grid, 256, SMEM_BYTES>>>(b1);

    snn_scan<<<SNN_B, 1024>>>(w2, b2, out_mem, out_spk);

    (void)in_sizes; (void)n_in; (void)out_size;
}

// round 12
// speedup vs baseline: 6.3584x; 6.3584x over previous
#include <cuda_runtime.h>
#include <cuda.h>
#include <cuda_bf16.h>
#include <cstdint>

// ---------------------------------------------------------------------------
// tcgen05 is arch-specific; the harness also builds a family-generic pass
// where it is illegal PTX. Guard ONLY the tcgen05 kernel. Fallback selection
// happens ON DEVICE via a completion counter (no host branching).
// ---------------------------------------------------------------------------
#if defined(__CUDA_ARCH_FEAT_SM103_ALL) || defined(__CUDA_ARCH_FEAT_SM100_ALL) || defined(__CUDA_ARCH_FEAT_SM101_ALL)
#define SNN_HAS_TCG 1
#else
#define SNN_HAS_TCG 0
#endif

#define SNN_B   128
#define SNN_T   200
#define SNN_NI  4096
#define SNN_NH  1024
#define SNN_NO  2
#define SNN_M   (SNN_B * SNN_T)
#define TC_CTAS 1600                     // (1024/128) x (25600/128)

// Interleaved slice layout: [row][chunk c(128)][slice p(4)][k'(32)] bf16.
// Row width = 128*4*32 = 16384 bf16 = 32768 B.
#define XI_W    16384
static __device__ __align__(256) __nv_bfloat16 g_Xi[(size_t)SNN_M * XI_W];  // 839MB
static __device__ __align__(256) __nv_bfloat16 g_Wi[(size_t)SNN_NH * XI_W]; //  34MB
static __device__ float g_cur1[(size_t)SNN_M * SNN_NH];                      // 100MB
static __device__ int   g_tc_done;

#define INV254F    0.003937007859349251f    // float(1/254)
#define INV64516F  1.5500031800032407e-05f  // float(1/254^2)
#define SCALE14    6.103515625e-05f         // 2^-14 = 1/(4*4096)

// ---------------------------------------------------------------------------
// Generic helpers
// ---------------------------------------------------------------------------
__device__ __forceinline__ uint32_t smem_u32(const void* p) {
    uint32_t a;
    asm("{ .reg .u64 t; cvta.to.shared.u64 t, %1; cvt.u32.u64 %0, t; }" : "=r"(a) : "l"(p));
    return a;
}
#define MBAR_INIT(addr, cnt) \
    asm volatile("mbarrier.init.shared.b64 [%0], %1;" :: "r"(addr), "r"(cnt) : "memory")
#define MBAR_EXPECT_TX(addr, bytes) \
    asm volatile("mbarrier.arrive.expect_tx.shared.b64 _, [%0], %1;" :: "r"(addr), "r"(bytes) : "memory")
#define MBAR_WAIT(addr, phase) do {                                              \
    asm volatile("{\n\t.reg .pred P1;\n\t"                                       \
        "WAIT_LOOP_%=:\n\t"                                                      \
        "mbarrier.try_wait.parity.acquire.cta.shared::cta.b64 P1, [%0], %1, 0x989680;\n\t" \
        "@P1 bra.uni WAIT_DONE_%=;\n\t"                                          \
        "bra.uni WAIT_LOOP_%=;\n\t"                                              \
        "WAIT_DONE_%=:\n\t}"                                                     \
        :: "r"((uint32_t)(addr)), "r"((uint32_t)(phase)) : "memory");            \
} while (0)

#if SNN_HAS_TCG
#define TCG_ALLOC(smem_addr, ncols) \
    asm volatile("tcgen05.alloc.cta_group::1.sync.aligned.shared::cta.b32 [%0], %1;" \
                 :: "r"(smem_addr), "r"(ncols) : "memory")
#define TCG_RELINQ() \
    asm volatile("tcgen05.relinquish_alloc_permit.cta_group::1.sync.aligned;")
#define TCG_DEALLOC(tmem, ncols) \
    asm volatile("tcgen05.dealloc.cta_group::1.sync.aligned.b32 %0, %1;" :: "r"(tmem), "r"(ncols))
#define TCG_COMMIT(mbar) \
    asm volatile("tcgen05.commit.cta_group::1.mbarrier::arrive::one.shared::cluster.b64 [%0];" \
                 :: "r"(mbar) : "memory")
#define TCG_FENCE_AFTER()  asm volatile("tcgen05.fence::after_thread_sync;" ::: "memory")
#define TCG_FENCE_BEFORE() asm volatile("tcgen05.fence::before_thread_sync;" ::: "memory")
#define TCG_WAIT_LD()      asm volatile("tcgen05.wait::ld.sync.aligned;" ::: "memory")
#define TCG_LD_X32(r, tmem_addr) \
    asm volatile( \
        "tcgen05.ld.sync.aligned.32x32b.x32.b32 " \
        "{%0, %1, %2, %3, %4, %5, %6, %7, " \
        " %8, %9, %10, %11, %12, %13, %14, %15, " \
        " %16, %17, %18, %19, %20, %21, %22, %23, " \
        " %24, %25, %26, %27, %28, %29, %30, %31}, [%32];" \
        : "=r"((r)[0]),  "=r"((r)[1]),  "=r"((r)[2]),  "=r"((r)[3]), \
          "=r"((r)[4]),  "=r"((r)[5]),  "=r"((r)[6]),  "=r"((r)[7]), \
          "=r"((r)[8]),  "=r"((r)[9]),  "=r"((r)[10]), "=r"((r)[11]), \
          "=r"((r)[12]), "=r"((r)[13]), "=r"((r)[14]), "=r"((r)[15]), \
          "=r"((r)[16]), "=r"((r)[17]), "=r"((r)[18]), "=r"((r)[19]), \
          "=r"((r)[20]), "=r"((r)[21]), "=r"((r)[22]), "=r"((r)[23]), \
          "=r"((r)[24]), "=r"((r)[25]), "=r"((r)[26]), "=r"((r)[27]), \
          "=r"((r)[28]), "=r"((r)[29]), "=r"((r)[30]), "=r"((r)[31]) \
        : "r"(tmem_addr))

__device__ __forceinline__ void mma_bf16_ss(uint32_t d, uint64_t adesc, uint64_t bdesc,
                                            uint32_t idesc, uint32_t en) {
    asm volatile(
        "{\n\t.reg .pred p;\n\tsetp.ne.u32 p, %5, 0;\n\t"
        "tcgen05.mma.cta_group::1.kind::f16 [%0], %1, %2, %3, {%4, %4, %4, %4}, p;\n\t}"
        :: "r"(d), "l"(adesc), "l"(bdesc), "r"(idesc), "r"(0u), "r"(en) : "memory");
}
__device__ __forceinline__ void tma2d(uint32_t smem_addr, const CUtensorMap* tm,
                                      int cx, int cy, uint32_t mbar) {
    asm volatile(
        "cp.async.bulk.tensor.2d.shared::cta.global.tile.mbarrier::complete_tx::bytes "
        "[%0], [%1, {%2, %3}], [%4];"
        :: "r"(smem_addr), "l"(tm), "r"(cx), "r"(cy), "r"(mbar) : "memory");
}
// SW128 K-major descriptor (LBO=1, SBO=64, version=1) -- R11-proven
__device__ __forceinline__ uint64_t make_desc(uint32_t addr) {
    const uint64_t base = (uint64_t(2) << 61) | (uint64_t(1) << 46)
                        | (uint64_t(64) << 32) | (uint64_t(1) << 16);
    return base | ((uint64_t)(addr >> 4) & 0x3FFF);
}
#endif // SNN_HAS_TCG

// ---------------------------------------------------------------------------
// Quantization: v*S = q0 + q1/254 + q2/254^2 + q3/254^3 + e, |e|<=0.5/254^3.
// |q_i| <= 127 by radix-254 construction; slices exact in bf16.
// Writes interleaved layout: [row][c][slice][k'].
// ---------------------------------------------------------------------------
__device__ __forceinline__ void quant4_store(float4 v, float S,
                                             __nv_bfloat16* base, size_t row,
                                             int c, int kk) {
    float e[4] = {v.x * S, v.y * S, v.z * S, v.w * S};
    float q0[4], q1[4], q2[4], q3[4];
#pragma unroll
    for (int j = 0; j < 4; j++) {
        q0[j] = rintf(e[j]);
        float r = e[j] - q0[j];
        q1[j] = rintf(r * 254.f);
        r = fmaf(q1[j], -INV254F, r);
        q2[j] = rintf(r * 64516.f);
        r = fmaf(q2[j], -INV64516F, r);
        q3[j] = rintf(r * 16387064.f);        // 254^3
    }
    float* qs[4] = {q0, q1, q2, q3};
    __nv_bfloat16* rowp = base + row * XI_W + (size_t)c * 128 + kk;
#pragma unroll
    for (int p = 0; p < 4; p++) {
        uint32_t lo, hi;
        asm("cvt.rn.bf16x2.f32 %0, %1, %2;" : "=r"(lo) : "f"(qs[p][1]), "f"(qs[p][0]));
        asm("cvt.rn.bf16x2.f32 %0, %1, %2;" : "=r"(hi) : "f"(qs[p][3]), "f"(qs[p][2]));
        *(uint2*)(rowp + p * 32) = make_uint2(lo, hi);
    }
}

__global__ __launch_bounds__(256)
void quantX(const float4* __restrict__ x, int n4) {
    int q = blockIdx.x * 256 + threadIdx.x;
    if (q == 0) g_tc_done = 0;               // reset flag each launch
    if (q >= n4) return;
    size_t row = (size_t)(q >> 10);
    int kq = q & 1023;                        // quad index in row
    quant4_store(x[q], 4.0f, g_Xi, row, kq >> 3, (kq & 7) * 4);
}
__global__ __launch_bounds__(256)
void quantW(const float4* __restrict__ w, int n4) {
    int q = blockIdx.x * 256 + threadIdx.x;
    if (q >= n4) return;
    size_t row = (size_t)(q >> 10);
    int kq = q & 1023;
    quant4_store(w[q], 4096.0f, g_Wi, row, kq >> 3, (kq & 7) * 4);
}

// ---------------------------------------------------------------------------
// Single extern shared symbol for the TU.
// ---------------------------------------------------------------------------
extern __shared__ __align__(1024) char g_smem[];

// ---------------------------------------------------------------------------
// fc1 on tcgen05: 4-slice radix-254, classes by weight w=i+j<=3 (10 MMAs per
// k16 step) into 4 TMEM accumulators (cols 0/128/256/384 = full 512).
// All class sums are integer-valued fp32 < 2^24 -> accumulation EXACT.
// CTA 128x128, K-chunk 32 (one interleaved 128-col TMA box pair per matrix),
// 2-stage, single-thread control (R11-proven machinery). 128 threads.
// ---------------------------------------------------------------------------
#define T_FULL(s)  (16 + 8 * (s))
#define T_DONE(s)  (32 + 8 * (s))
#define T_FIN      48
#define T_BIAS     64
#define T_DATA     1024
#define T_PL       16384                       // 128 rows x 128B (2 slices' k32)
#define T_STAGE    (4 * T_PL)                  // A01,A23,B01,B23 = 65536
#define T_SMEM     (T_DATA + 2 * T_STAGE)      // 132096
#define T_NCHUNK   128                         // k32 chunks

__global__ __launch_bounds__(128)
void fc1_tc(const __grid_constant__ CUtensorMap tmA,
            const __grid_constant__ CUtensorMap tmB,
            const float* __restrict__ bias) {
#if SNN_HAS_TCG
    char* smem = g_smem;
    uint32_t sb = smem_u32(smem);
    const int tid = threadIdx.x;
    const int wid = tid >> 5;
    const int lid = tid & 31;
    const int n0 = blockIdx.x * 128;
    const int m0 = blockIdx.y * 128;

    if (wid == 0) { TCG_ALLOC(sb + 0, 512); TCG_RELINQ(); }
    if (tid == 0) {
        MBAR_INIT(sb + T_FULL(0), 1);
        MBAR_INIT(sb + T_FULL(1), 1);
        MBAR_INIT(sb + T_DONE(0), 1);
        MBAR_INIT(sb + T_DONE(1), 1);
        MBAR_INIT(sb + T_FIN,     1);
        asm volatile("fence.proxy.async.shared::cta;" ::: "memory");
    }
    ((float*)(smem + T_BIAS))[tid] = __ldg(bias + n0 + tid);
    __syncthreads();

    uint32_t tb;
    asm volatile("ld.shared.b32 %0, [%1];" : "=r"(tb) : "r"(sb));

    if (tid == 0) {
        const uint32_t IDESC = (1u << 4) | (1u << 7) | (1u << 10)
                             | (16u << 17) | (8u << 24);   // f32, bf16, N=128, M=128
        // prime stage 0 with chunk 0
        {
            MBAR_EXPECT_TX(sb + T_FULL(0), T_STAGE);
            tma2d(sb + T_DATA + 0 * T_PL, &tmA, 0,  m0, sb + T_FULL(0));
            tma2d(sb + T_DATA + 1 * T_PL, &tmA, 64, m0, sb + T_FULL(0));
            tma2d(sb + T_DATA + 2 * T_PL, &tmB, 0,  n0, sb + T_FULL(0));
            tma2d(sb + T_DATA + 3 * T_PL, &tmB, 64, n0, sb + T_FULL(0));
        }
        for (int c = 0; c < T_NCHUNK; c++) {
            const int s = c & 1;
            if (c + 1 < T_NCHUNK) {
                const int sn = s ^ 1;
                if (c >= 1) MBAR_WAIT(sb + T_DONE(sn), ((c - 1) >> 1) & 1);
                MBAR_EXPECT_TX(sb + T_FULL(sn), T_STAGE);
                const int kx = (c + 1) * 128;
                uint32_t sd = sb + T_DATA + sn * T_STAGE;
                tma2d(sd + 0 * T_PL, &tmA, kx,      m0, sb + T_FULL(sn));
                tma2d(sd + 1 * T_PL, &tmA, kx + 64, m0, sb + T_FULL(sn));
                tma2d(sd + 2 * T_PL, &tmB, kx,      n0, sb + T_FULL(sn));
                tma2d(sd + 3 * T_PL, &tmB, kx + 64, n0, sb + T_FULL(sn));
            }
            MBAR_WAIT(sb + T_FULL(s), (c >> 1) & 1);
            const uint32_t sd = sb + T_DATA + s * T_STAGE;
            const uint64_t dA01 = make_desc(sd + 0 * T_PL);
            const uint64_t dA23 = make_desc(sd + 1 * T_PL);
            const uint64_t dB01 = make_desc(sd + 2 * T_PL);
            const uint64_t dB23 = make_desc(sd + 3 * T_PL);
#pragma unroll
            for (int ks = 0; ks < 2; ks++) {
                const uint64_t ko = ks * 2;    // 16 bf16 = 32B within 64B half
                // slice descriptors: plane holds [slice even | slice odd] 32B each... 
                // layout per 128B row: sliceE k'[0:32) bytes[0:64), sliceO bytes[64:128)
                const uint64_t a0 = dA01 + ko;       // slice0: bytes [0,64)
                const uint64_t a1 = dA01 + 4 + ko;   // slice1: bytes [64,128)
                const uint64_t a2 = dA23 + ko;
                const uint64_t a3 = dA23 + 4 + ko;
                const uint64_t b0 = dB01 + ko;
                const uint64_t b1 = dB01 + 4 + ko;
                const uint64_t b2 = dB23 + ko;
                const uint64_t b3 = dB23 + 4 + ko;
                const uint32_t ef = (c != 0 || ks != 0) ? 1u : 0u;
                mma_bf16_ss(tb,       a0, b0, IDESC, ef);  // w0
                mma_bf16_ss(tb + 128, a0, b1, IDESC, ef);  // w1
                mma_bf16_ss(tb + 128, a1, b0, IDESC, 1);
                mma_bf16_ss(tb + 256, a0, b2, IDESC, ef);  // w2
                mma_bf16_ss(tb + 256, a1, b1, IDESC, 1);
                mma_bf16_ss(tb + 256, a2, b0, IDESC, 1);
                mma_bf16_ss(tb + 384, a0, b3, IDESC, ef);  // w3
                mma_bf16_ss(tb + 384, a1, b2, IDESC, 1);
                mma_bf16_ss(tb + 384, a2, b1, IDESC, 1);
                mma_bf16_ss(tb + 384, a3, b0, IDESC, 1);
            }
            TCG_COMMIT(sb + T_DONE(s));
        }
        TCG_COMMIT(sb + T_FIN);
    }

    MBAR_WAIT(sb + T_FIN, 0);
    TCG_FENCE_AFTER();

    // epilogue: Horner over 4 exact class sums + bias -> g_cur1
    const float* bs = (const float*)(smem + T_BIAS);
    const int row = m0 + wid * 32 + lid;
    float* dst = g_cur1 + (size_t)row * SNN_NH + n0;
#pragma unroll 1
    for (int g = 0; g < 4; g++) {
        uint32_t c0[32], c1[32], c2[32], c3[32];
        TCG_LD_X32(c0, tb +       g * 32);
        TCG_LD_X32(c1, tb + 128 + g * 32);
        TCG_LD_X32(c2, tb + 256 + g * 32);
        TCG_LD_X32(c3, tb + 384 + g * 32);
        TCG_WAIT_LD();
#pragma unroll
        for (int j = 0; j < 32; j += 4) {
            float4 o;
#pragma unroll
            for (int t = 0; t < 4; t++) {
                float f = fmaf(__uint_as_float(c3[j + t]), INV254F,
                               __uint_as_float(c2[j + t]));
                f = fmaf(f, INV254F, __uint_as_float(c1[j + t]));
                f = fmaf(f, INV254F, __uint_as_float(c0[j + t]));
                ((float*)&o)[t] = fmaf(f, SCALE14, bs[g * 32 + j + t]);
            }
            *(float4*)(dst + g * 32 + j) = o;
        }
    }
    TCG_FENCE_BEFORE();
    __syncthreads();
    if (wid == 0) TCG_DEALLOC(tb, 512);
    if (tid == 0) atomicAdd(&g_tc_done, 1);
#endif // SNN_HAS_TCG
}

// ---------------------------------------------------------------------------
// Fallback: R1-PROVEN fp32 FFMA GEMM on raw inputs (passed at 7.68ms,
// rel_err 2.4e-4). Early-exits if the tcgen05 grid completed.
// ---------------------------------------------------------------------------
__global__ __launch_bounds__(256)
void fc1_ffma(const float* __restrict__ A,
              const float* __restrict__ W,
              const float* __restrict__ bias)
{
    if (g_tc_done == TC_CTAS) return;

    const int K = SNN_NI;
    __shared__ float As[16][128];
    __shared__ float Ws[16][128];

    const int tid  = threadIdx.x;
    const int bn   = blockIdx.x;
    const int bm   = blockIdx.y;
    const int lrow = tid >> 2;
    const int lc4  = (tid & 3) << 2;
    const int tx   = tid & 15;
    const int ty   = tid >> 4;

    const float* Ab = A + (size_t)bm * 128 * K;
    const float* Wb = W + (size_t)bn * 128 * K;

    float acc[8][8];
#pragma unroll
    for (int i = 0; i < 8; i++)
#pragma unroll
        for (int j = 0; j < 8; j++) acc[i][j] = 0.f;

    for (int k0 = 0; k0 < K; k0 += 16) {
        float4 a0 = *(const float4*)(Ab + (size_t)lrow        * K + k0 + lc4);
        float4 a1 = *(const float4*)(Ab + (size_t)(lrow + 64) * K + k0 + lc4);
        float4 w0 = *(const float4*)(Wb + (size_t)lrow        * K + k0 + lc4);
        float4 w1 = *(const float4*)(Wb + (size_t)(lrow + 64) * K + k0 + lc4);

        __syncthreads();
        As[lc4 + 0][lrow]      = a0.x;
        As[lc4 + 1][lrow]      = a0.y;
        As[lc4 + 2][lrow]      = a0.z;
        As[lc4 + 3][lrow]      = a0.w;
        As[lc4 + 0][lrow + 64] = a1.x;
        As[lc4 + 1][lrow + 64] = a1.y;
        As[lc4 + 2][lrow + 64] = a1.z;
        As[lc4 + 3][lrow + 64] = a1.w;
        Ws[lc4 + 0][lrow]      = w0.x;
        Ws[lc4 + 1][lrow]      = w0.y;
        Ws[lc4 + 2][lrow]      = w0.z;
        Ws[lc4 + 3][lrow]      = w0.w;
        Ws[lc4 + 0][lrow + 64] = w1.x;
        Ws[lc4 + 1][lrow + 64] = w1.y;
        Ws[lc4 + 2][lrow + 64] = w1.z;
        Ws[lc4 + 3][lrow + 64] = w1.w;
        __syncthreads();

#pragma unroll
        for (int kk = 0; kk < 16; kk++) {
            float ar[8], br[8];
            *(float4*)(ar)     = *(const float4*)&As[kk][ty * 8];
            *(float4*)(ar + 4) = *(const float4*)&As[kk][ty * 8 + 4];
            *(float4*)(br)     = *(const float4*)&Ws[kk][tx * 8];
            *(float4*)(br + 4) = *(const float4*)&Ws[kk][tx * 8 + 4];
#pragma unroll
            for (int i = 0; i < 8; i++)
#pragma unroll
                for (int j = 0; j < 8; j++)
                    acc[i][j] = fmaf(ar[i], br[j], acc[i][j]);
        }
    }

    const int n0 = bn * 128 + tx * 8;
    const int m0 = bm * 128 + ty * 8;
    float bv[8];
#pragma unroll
    for (int j = 0; j < 8; j++) bv[j] = bias[n0 + j];

#pragma unroll
    for (int i = 0; i < 8; i++) {
        float4 o0, o1;
        o0.x = acc[i][0] + bv[0];
        o0.y = acc[i][1] + bv[1];
        o0.z = acc[i][2] + bv[2];
        o0.w = acc[i][3] + bv[3];
        o1.x = acc[i][4] + bv[4];
        o1.y = acc[i][5] + bv[5];
        o1.z = acc[i][6] + bv[6];
        o1.w = acc[i][7] + bv[7];
        float* Crow = g_cur1 + (size_t)(m0 + i) * SNN_NH + n0;
        *(float4*)(Crow)     = o0;
        *(float4*)(Crow + 4) = o1;
    }
}

// ---------------------------------------------------------------------------
// sequential SNN scan (R1-proven)
// ---------------------------------------------------------------------------
__global__ __launch_bounds__(1024)
void snn_scan(const float* __restrict__ w2, const float* __restrict__ b2,
              float* __restrict__ out_mem, float* __restrict__ out_spk) {
    const int b = blockIdx.x;
    const int h = threadIdx.x;
    const float ALPHA = 0.8187307530779818f;
    const float BETA  = 0.9048374180359595f;

    __shared__ float red0[32];
    __shared__ float red1[32];

    const float w20 = w2[h];
    const float w21 = w2[SNN_NH + h];
    const float b20 = b2[0];
    const float b21 = b2[1];

    float syn1 = 0.f, mem1 = 0.f;
    float syn2a = 0.f, mem2a = 0.f, syn2b = 0.f, mem2b = 0.f;

    const float* cp = g_cur1 + (size_t)b * SNN_T * SNN_NH + h;
    float cur_next = cp[0];

    const int lane = h & 31;
    const int warp = h >> 5;

    for (int t = 0; t < SNN_T; t++) {
        float cur = cur_next;
        if (t + 1 < SNN_T) cur_next = cp[(size_t)(t + 1) * SNN_NH];

        float r1 = (mem1 > 1.0f) ? 1.0f : 0.0f;
        syn1 = fmaf(ALPHA, syn1, cur);
        mem1 = fmaf(BETA, mem1, syn1) - r1;
        float spk = (mem1 > 1.0f) ? 1.0f : 0.0f;

        float v0 = spk * w20;
        float v1 = spk * w21;
#pragma unroll
        for (int off = 16; off > 0; off >>= 1) {
            v0 += __shfl_down_sync(0xffffffffu, v0, off);
            v1 += __shfl_down_sync(0xffffffffu, v1, off);
        }
        if (lane == 0) { red0[warp] = v0; red1[warp] = v1; }
        __syncthreads();

        if (h < 32) {
            float s0 = red0[h];
            float s1 = red1[h];
#pragma unroll
            for (int off = 16; off > 0; off >>= 1) {
                s0 += __shfl_down_sync(0xffffffffu, s0, off);
                s1 += __shfl_down_sync(0xffffffffu, s1, off);
            }
            if (h == 0) {
                float c0 = s0 + b20;
                float c1 = s1 + b21;
                float r2a = (mem2a > 1.0f) ? 1.0f : 0.0f;
                float r2b = (mem2b > 1.0f) ? 1.0f : 0.0f;
                syn2a = fmaf(ALPHA, syn2a, c0);
                syn2b = fmaf(ALPHA, syn2b, c1);
                mem2a = fmaf(BETA, mem2a, syn2a) - r2a;
                mem2b = fmaf(BETA, mem2b, syn2b) - r2b;
                size_t o = ((size_t)b * SNN_T + t) * 2;
                out_mem[o]     = mem2a;
                out_mem[o + 1] = mem2b;
                out_spk[o]     = (mem2a > 1.0f) ? 1.0f : 0.0f;
                out_spk[o + 1] = (mem2b > 1.0f) ? 1.0f : 0.0f;
            }
        }
        __syncthreads();
    }
}

// ---------------------------------------------------------------------------
// Launch: unconditional sequence; device-side flag picks the GEMM that wins.
// ---------------------------------------------------------------------------
typedef CUresult (*PFN_tmap_encode)(
    CUtensorMap*, CUtensorMapDataType, cuuint32_t, void*,
    const cuuint64_t*, const cuuint64_t*, const cuuint32_t*, const cuuint32_t*,
    CUtensorMapInterleave, CUtensorMapSwizzle, CUtensorMapL2promotion,
    CUtensorMapFloatOOBfill);

extern "C" void kernel_launch(void* const* d_in, const int* in_sizes, int n_in,
                              void* d_out, int out_size) {
    const float* x  = (const float*)d_in[0];
    const float* w1 = (const float*)d_in[1];
    const float* b1 = (const float*)d_in[2];
    const float* w2 = (const float*)d_in[3];
    const float* b2 = (const float*)d_in[4];
    float* out = (float*)d_out;
    float* out_mem = out;
    float* out_spk = out + (size_t)SNN_B * SNN_T * SNN_NO;

    void* aPtr = nullptr;
    void* wPtr = nullptr;
    cudaGetSymbolAddress(&aPtr, g_Xi);
    cudaGetSymbolAddress(&wPtr, g_Wi);

    CUtensorMap tmA = {}, tmB = {};
    PFN_tmap_encode pfn = nullptr;
    cudaDriverEntryPointQueryResult qres;
    cudaGetDriverEntryPoint("cuTensorMapEncodeTiled", (void**)&pfn,
                            cudaEnableDefault, &qres);
    if (pfn && aPtr && wPtr) {
        cuuint64_t dimsA[2]   = {XI_W, SNN_M};
        cuuint64_t strideA[1] = {XI_W * 2};
        cuuint32_t box[2]     = {64, 128};
        cuuint32_t est[2]     = {1, 1};
        pfn(&tmA, CU_TENSOR_MAP_DATA_TYPE_BFLOAT16, 2, aPtr, dimsA, strideA,
            box, est, CU_TENSOR_MAP_INTERLEAVE_NONE, CU_TENSOR_MAP_SWIZZLE_128B,
            CU_TENSOR_MAP_L2_PROMOTION_L2_128B, CU_TENSOR_MAP_FLOAT_OOB_FILL_NONE);
        cuuint64_t dimsB[2]   = {XI_W, SNN_NH};
        cuuint64_t strideB[1] = {XI_W * 2};
        pfn(&tmB, CU_TENSOR_MAP_DATA_TYPE_BFLOAT16, 2, wPtr, dimsB, strideB,
            box, est, CU_TENSOR_MAP_INTERLEAVE_NONE, CU_TENSOR_MAP_SWIZZLE_128B,
            CU_TENSOR_MAP_L2_PROMOTION_L2_128B, CU_TENSOR_MAP_FLOAT_OOB_FILL_NONE);
    }

    cudaFuncSetAttribute(fc1_tc, cudaFuncAttributeMaxDynamicSharedMemorySize, T_SMEM);

    const int nx4 = SNN_M * SNN_NI / 4;
    const int nw4 = SNN_NH * SNN_NI / 4;
    quantX<<<(nx4 + 255) / 256, 256>>>((const float4*)x, nx4);   // also resets flag
    quantW<<<(nw4 + 255) / 256, 256>>>((const float4*)w1, nw4);

    // tcgen05 attempt (stub or failed launch leaves flag at 0)
    dim3 grid_tc(SNN_NH / 128, SNN_M / 128);   // (8, 200)
    fc1_tc<<<grid_tc, 128, T_SMEM>>>(tmA, tmB, b1);

    // proven fp32 FFMA fallback (early-exits if tcgen05 completed)
    dim3 grid_ff(SNN_NH / 128, SNN_M / 128);   // (8, 200)
    fc1_ffma<<<grid_ff, 256>>>(x, w1, b1);

    snn_scan<<<SNN_B, 1024>>>(w2, b2, out_mem, out_spk);

    (void)in_sizes; (void)n_in; (void)out_size;
}

// round 13
// speedup vs baseline: 9.4019x; 1.4787x over previous
#include <cuda_runtime.h>
#include <cuda.h>
#include <cuda_bf16.h>
#include <cstdint>

// ---------------------------------------------------------------------------
// tcgen05 is arch-specific; guard ONLY the tcgen05 kernel (harness also builds
// a family-generic pass). Fallback selection happens on device via g_tc_done.
// R12 PROVED the tcgen05 path executes (fallback folded to 6.4us).
// ---------------------------------------------------------------------------
#if defined(__CUDA_ARCH_FEAT_SM103_ALL) || defined(__CUDA_ARCH_FEAT_SM100_ALL) || defined(__CUDA_ARCH_FEAT_SM101_ALL)
#define SNN_HAS_TCG 1
#else
#define SNN_HAS_TCG 0
#endif

#define SNN_B   128
#define SNN_T   200
#define SNN_NI  4096
#define SNN_NH  1024
#define SNN_NO  2
#define SNN_M   (SNN_B * SNN_T)
#define TC_CTAS 1600                     // (1024/128) x (25600/128)

// Interleaved slice layout: [row][chunk c(128)][slice p(4)][k'(32)] bf16.
#define XI_W    16384
static __device__ __align__(256) __nv_bfloat16 g_Xi[(size_t)SNN_M * XI_W];  // 839MB
static __device__ __align__(256) __nv_bfloat16 g_Wi[(size_t)SNN_NH * XI_W]; //  34MB
static __device__ float g_cur1[(size_t)SNN_M * SNN_NH];                      // 100MB
static __device__ int   g_tc_done;

#define INV254F    0.003937007859349251f    // float(1/254)
#define INV64516F  1.5500031800032407e-05f  // float(1/254^2)
#define SCALE14    6.103515625e-05f         // 2^-14 = 1/(4*4096)

// ---------------------------------------------------------------------------
// Generic helpers
// ---------------------------------------------------------------------------
__device__ __forceinline__ uint32_t smem_u32(const void* p) {
    uint32_t a;
    asm("{ .reg .u64 t; cvta.to.shared.u64 t, %1; cvt.u32.u64 %0, t; }" : "=r"(a) : "l"(p));
    return a;
}
#define MBAR_INIT(addr, cnt) \
    asm volatile("mbarrier.init.shared.b64 [%0], %1;" :: "r"(addr), "r"(cnt) : "memory")
#define MBAR_EXPECT_TX(addr, bytes) \
    asm volatile("mbarrier.arrive.expect_tx.shared.b64 _, [%0], %1;" :: "r"(addr), "r"(bytes) : "memory")
#define MBAR_WAIT(addr, phase) do {                                              \
    asm volatile("{\n\t.reg .pred P1;\n\t"                                       \
        "WAIT_LOOP_%=:\n\t"                                                      \
        "mbarrier.try_wait.parity.acquire.cta.shared::cta.b64 P1, [%0], %1, 0x989680;\n\t" \
        "@P1 bra.uni WAIT_DONE_%=;\n\t"                                          \
        "bra.uni WAIT_LOOP_%=;\n\t"                                              \
        "WAIT_DONE_%=:\n\t}"                                                     \
        :: "r"((uint32_t)(addr)), "r"((uint32_t)(phase)) : "memory");            \
} while (0)
#define CLUSTER_SYNC() do { \
    asm volatile("barrier.cluster.arrive.aligned;" ::: "memory"); \
    asm volatile("barrier.cluster.wait.aligned;" ::: "memory"); \
} while (0)

#if SNN_HAS_TCG
#define TCG_ALLOC(smem_addr, ncols) \
    asm volatile("tcgen05.alloc.cta_group::1.sync.aligned.shared::cta.b32 [%0], %1;" \
                 :: "r"(smem_addr), "r"(ncols) : "memory")
#define TCG_RELINQ() \
    asm volatile("tcgen05.relinquish_alloc_permit.cta_group::1.sync.aligned;")
#define TCG_DEALLOC(tmem, ncols) \
    asm volatile("tcgen05.dealloc.cta_group::1.sync.aligned.b32 %0, %1;" :: "r"(tmem), "r"(ncols))
#define TCG_COMMIT(mbar) \
    asm volatile("tcgen05.commit.cta_group::1.mbarrier::arrive::one.shared::cluster.b64 [%0];" \
                 :: "r"(mbar) : "memory")
#define TCG_COMMIT_MC(mbar, mask) \
    asm volatile("tcgen05.commit.cta_group::1.mbarrier::arrive::one.shared::cluster.multicast::cluster.b64 [%0], %1;" \
                 :: "r"(mbar), "h"((uint16_t)(mask)) : "memory")
#define TCG_FENCE_AFTER()  asm volatile("tcgen05.fence::after_thread_sync;" ::: "memory")
#define TCG_FENCE_BEFORE() asm volatile("tcgen05.fence::before_thread_sync;" ::: "memory")
#define TCG_WAIT_LD()      asm volatile("tcgen05.wait::ld.sync.aligned;" ::: "memory")
#define TCG_LD_X32(r, tmem_addr) \
    asm volatile( \
        "tcgen05.ld.sync.aligned.32x32b.x32.b32 " \
        "{%0, %1, %2, %3, %4, %5, %6, %7, " \
        " %8, %9, %10, %11, %12, %13, %14, %15, " \
        " %16, %17, %18, %19, %20, %21, %22, %23, " \
        " %24, %25, %26, %27, %28, %29, %30, %31}, [%32];" \
        : "=r"((r)[0]),  "=r"((r)[1]),  "=r"((r)[2]),  "=r"((r)[3]), \
          "=r"((r)[4]),  "=r"((r)[5]),  "=r"((r)[6]),  "=r"((r)[7]), \
          "=r"((r)[8]),  "=r"((r)[9]),  "=r"((r)[10]), "=r"((r)[11]), \
          "=r"((r)[12]), "=r"((r)[13]), "=r"((r)[14]), "=r"((r)[15]), \
          "=r"((r)[16]), "=r"((r)[17]), "=r"((r)[18]), "=r"((r)[19]), \
          "=r"((r)[20]), "=r"((r)[21]), "=r"((r)[22]), "=r"((r)[23]), \
          "=r"((r)[24]), "=r"((r)[25]), "=r"((r)[26]), "=r"((r)[27]), \
          "=r"((r)[28]), "=r"((r)[29]), "=r"((r)[30]), "=r"((r)[31]) \
        : "r"(tmem_addr))

__device__ __forceinline__ void mma_bf16_ss(uint32_t d, uint64_t adesc, uint64_t bdesc,
                                            uint32_t idesc, uint32_t en) {
    asm volatile(
        "{\n\t.reg .pred p;\n\tsetp.ne.u32 p, %5, 0;\n\t"
        "tcgen05.mma.cta_group::1.kind::f16 [%0], %1, %2, %3, {%4, %4, %4, %4}, p;\n\t}"
        :: "r"(d), "l"(adesc), "l"(bdesc), "r"(idesc), "r"(0u), "r"(en) : "memory");
}
__device__ __forceinline__ void tma2d(uint32_t smem_addr, const CUtensorMap* tm,
                                      int cx, int cy, uint32_t mbar) {
    asm volatile(
        "cp.async.bulk.tensor.2d.shared::cta.global.tile.mbarrier::complete_tx::bytes "
        "[%0], [%1, {%2, %3}], [%4];"
        :: "r"(smem_addr), "l"(tm), "r"(cx), "r"(cy), "r"(mbar) : "memory");
}
// Multicast 2D TMA: delivers data + complete_tx to the same smem offset in
// every CTA whose bit is set in the cluster mask.
__device__ __forceinline__ void tma2d_mc(uint32_t smem_addr, const CUtensorMap* tm,
                                         int cx, int cy, uint32_t mbar, uint16_t mask) {
    asm volatile(
        "cp.async.bulk.tensor.2d.shared::cluster.global.tile.mbarrier::complete_tx::bytes.multicast::cluster "
        "[%0], [%1, {%2, %3}], [%4], %5;"
        :: "r"(smem_addr), "l"(tm), "r"(cx), "r"(cy), "r"(mbar), "h"(mask) : "memory");
}
__device__ __forceinline__ uint32_t cluster_rank() {
    uint32_t r;
    asm("mov.u32 %0, %%cluster_ctarank;" : "=r"(r));
    return r;
}
// SW128 K-major descriptor (LBO=1, SBO=64, version=1) -- R12-proven
__device__ __forceinline__ uint64_t make_desc(uint32_t addr) {
    const uint64_t base = (uint64_t(2) << 61) | (uint64_t(1) << 46)
                        | (uint64_t(64) << 32) | (uint64_t(1) << 16);
    return base | ((uint64_t)(addr >> 4) & 0x3FFF);
}
#endif // SNN_HAS_TCG

// ---------------------------------------------------------------------------
// Quantization (R12-proven): 4 radix-254 slices, exact in bf16, interleaved.
// ---------------------------------------------------------------------------
__device__ __forceinline__ void quant4_store(float4 v, float S,
                                             __nv_bfloat16* base, size_t row,
                                             int c, int kk) {
    float e[4] = {v.x * S, v.y * S, v.z * S, v.w * S};
    float q0[4], q1[4], q2[4], q3[4];
#pragma unroll
    for (int j = 0; j < 4; j++) {
        q0[j] = rintf(e[j]);
        float r = e[j] - q0[j];
        q1[j] = rintf(r * 254.f);
        r = fmaf(q1[j], -INV254F, r);
        q2[j] = rintf(r * 64516.f);
        r = fmaf(q2[j], -INV64516F, r);
        q3[j] = rintf(r * 16387064.f);        // 254^3
    }
    float* qs[4] = {q0, q1, q2, q3};
    __nv_bfloat16* rowp = base + row * XI_W + (size_t)c * 128 + kk;
#pragma unroll
    for (int p = 0; p < 4; p++) {
        uint32_t lo, hi;
        asm("cvt.rn.bf16x2.f32 %0, %1, %2;" : "=r"(lo) : "f"(qs[p][1]), "f"(qs[p][0]));
        asm("cvt.rn.bf16x2.f32 %0, %1, %2;" : "=r"(hi) : "f"(qs[p][3]), "f"(qs[p][2]));
        *(uint2*)(rowp + p * 32) = make_uint2(lo, hi);
    }
}

__global__ __launch_bounds__(256)
void quantX(const float4* __restrict__ x, int n4) {
    int q = blockIdx.x * 256 + threadIdx.x;
    if (q == 0) g_tc_done = 0;
    if (q >= n4) return;
    size_t row = (size_t)(q >> 10);
    int kq = q & 1023;
    quant4_store(x[q], 4.0f, g_Xi, row, kq >> 3, (kq & 7) * 4);
}
__global__ __launch_bounds__(256)
void quantW(const float4* __restrict__ w, int n4) {
    int q = blockIdx.x * 256 + threadIdx.x;
    if (q >= n4) return;
    size_t row = (size_t)(q >> 10);
    int kq = q & 1023;
    quant4_store(w[q], 4096.0f, g_Wi, row, kq >> 3, (kq & 7) * 4);
}

extern __shared__ __align__(1024) char g_smem[];

// ---------------------------------------------------------------------------
// fc1 on tcgen05 (R12-proven core) + NEW: 2-CTA cluster A-multicast.
// The two CTAs of a cluster share m0 (adjacent n-blocks). Each multicasts one
// 16KB A-half to both; B stays per-CTA. Per-SM LTS per chunk: 48KB < MMA
// floor (1280cyc) -> MMA-bound. Cross-CTA stage reuse is protected by DONE
// barriers (count=2) armed by commit-multicast from BOTH CTAs.
// ---------------------------------------------------------------------------
#define T_FULL(s)  (16 + 8 * (s))
#define T_DONE(s)  (32 + 8 * (s))
#define T_FIN      48
#define T_BIAS     64
#define T_DATA     1024
#define T_PL       16384
#define T_STAGE    (4 * T_PL)                  // A01,A23,B01,B23 = 65536
#define T_SMEM     (T_DATA + 2 * T_STAGE)      // 132096
#define T_NCHUNK   128

__global__ __launch_bounds__(128) __cluster_dims__(2, 1, 1)
void fc1_tc(const __grid_constant__ CUtensorMap tmA,
            const __grid_constant__ CUtensorMap tmB,
            const float* __restrict__ bias) {
#if SNN_HAS_TCG
    char* smem = g_smem;
    uint32_t sb = smem_u32(smem);
    const int tid = threadIdx.x;
    const int wid = tid >> 5;
    const int lid = tid & 31;
    const int n0 = blockIdx.x * 128;
    const int m0 = blockIdx.y * 128;
    const uint32_t rank = cluster_rank();     // blockIdx.x & 1

    if (wid == 0) { TCG_ALLOC(sb + 0, 512); TCG_RELINQ(); }
    if (tid == 0) {
        MBAR_INIT(sb + T_FULL(0), 1);
        MBAR_INIT(sb + T_FULL(1), 1);
        MBAR_INIT(sb + T_DONE(0), 2);          // both CTAs' commits arrive
        MBAR_INIT(sb + T_DONE(1), 2);
        MBAR_INIT(sb + T_FIN,     1);
        asm volatile("fence.proxy.async.shared::cta;" ::: "memory");
    }
    ((float*)(smem + T_BIAS))[tid] = __ldg(bias + n0 + tid);
    __syncthreads();
    CLUSTER_SYNC();                            // peer barriers live before MC TMA

    uint32_t tb;
    asm volatile("ld.shared.b32 %0, [%1];" : "=r"(tb) : "r"(sb));

    if (tid == 0) {
        const uint32_t IDESC = (1u << 4) | (1u << 7) | (1u << 10)
                             | (16u << 17) | (8u << 24);   // f32, bf16, N=128, M=128
        const uint16_t MC = 0x3;
        // prime stage 0: my A-half multicast to both, own B unicast
        {
            MBAR_EXPECT_TX(sb + T_FULL(0), T_STAGE);       // 16K+16K(A) + 32K(B)
            tma2d_mc(sb + T_DATA + rank * T_PL, &tmA, 64 * rank, m0,
                     sb + T_FULL(0), MC);
            tma2d(sb + T_DATA + 2 * T_PL, &tmB, 0,  n0, sb + T_FULL(0));
            tma2d(sb + T_DATA + 3 * T_PL, &tmB, 64, n0, sb + T_FULL(0));
        }
        for (int c = 0; c < T_NCHUNK; c++) {
            const int s = c & 1;
            if (c + 1 < T_NCHUNK) {
                const int sn = s ^ 1;
                // stage sn free only when BOTH CTAs' MMAs of chunk c-1 done
                if (c >= 1) MBAR_WAIT(sb + T_DONE(sn), ((c - 1) >> 1) & 1);
                MBAR_EXPECT_TX(sb + T_FULL(sn), T_STAGE);
                const int kx = (c + 1) * 128;
                uint32_t sd = sb + T_DATA + sn * T_STAGE;
                tma2d_mc(sd + rank * T_PL, &tmA, kx + 64 * rank, m0,
                         sb + T_FULL(sn), MC);
                tma2d(sd + 2 * T_PL, &tmB, kx,      n0, sb + T_FULL(sn));
                tma2d(sd + 3 * T_PL, &tmB, kx + 64, n0, sb + T_FULL(sn));
            }
            MBAR_WAIT(sb + T_FULL(s), (c >> 1) & 1);
            const uint32_t sd = sb + T_DATA + s * T_STAGE;
            const uint64_t dA01 = make_desc(sd + 0 * T_PL);
            const uint64_t dA23 = make_desc(sd + 1 * T_PL);
            const uint64_t dB01 = make_desc(sd + 2 * T_PL);
            const uint64_t dB23 = make_desc(sd + 3 * T_PL);
#pragma unroll
            for (int ks = 0; ks < 2; ks++) {
                const uint64_t ko = ks * 2;
                const uint64_t a0 = dA01 + ko;
                const uint64_t a1 = dA01 + 4 + ko;
                const uint64_t a2 = dA23 + ko;
                const uint64_t a3 = dA23 + 4 + ko;
                const uint64_t b0 = dB01 + ko;
                const uint64_t b1 = dB01 + 4 + ko;
                const uint64_t b2 = dB23 + ko;
                const uint64_t b3 = dB23 + 4 + ko;
                const uint32_t ef = (c != 0 || ks != 0) ? 1u : 0u;
                mma_bf16_ss(tb,       a0, b0, IDESC, ef);  // w0
                mma_bf16_ss(tb + 128, a0, b1, IDESC, ef);  // w1
                mma_bf16_ss(tb + 128, a1, b0, IDESC, 1);
                mma_bf16_ss(tb + 256, a0, b2, IDESC, ef);  // w2
                mma_bf16_ss(tb + 256, a1, b1, IDESC, 1);
                mma_bf16_ss(tb + 256, a2, b0, IDESC, 1);
                mma_bf16_ss(tb + 384, a0, b3, IDESC, ef);  // w3
                mma_bf16_ss(tb + 384, a1, b2, IDESC, 1);
                mma_bf16_ss(tb + 384, a2, b1, IDESC, 1);
                mma_bf16_ss(tb + 384, a3, b0, IDESC, 1);
            }
            // arrive on BOTH CTAs' DONE(s): stage reusable cluster-wide
            TCG_COMMIT_MC(sb + T_DONE(s), MC);
        }
        TCG_COMMIT(sb + T_FIN);
    }

    MBAR_WAIT(sb + T_FIN, 0);
    TCG_FENCE_AFTER();

    // epilogue: Horner over 4 exact class sums + bias -> g_cur1 (R12-proven)
    const float* bs = (const float*)(smem + T_BIAS);
    const int row = m0 + wid * 32 + lid;
    float* dst = g_cur1 + (size_t)row * SNN_NH + n0;
#pragma unroll 1
    for (int g = 0; g < 4; g++) {
        uint32_t c0[32], c1[32], c2[32], c3[32];
        TCG_LD_X32(c0, tb +       g * 32);
        TCG_LD_X32(c1, tb + 128 + g * 32);
        TCG_LD_X32(c2, tb + 256 + g * 32);
        TCG_LD_X32(c3, tb + 384 + g * 32);
        TCG_WAIT_LD();
#pragma unroll
        for (int j = 0; j < 32; j += 4) {
            float4 o;
#pragma unroll
            for (int t = 0; t < 4; t++) {
                float f = fmaf(__uint_as_float(c3[j + t]), INV254F,
                               __uint_as_float(c2[j + t]));
                f = fmaf(f, INV254F, __uint_as_float(c1[j + t]));
                f = fmaf(f, INV254F, __uint_as_float(c0[j + t]));
                ((float*)&o)[t] = fmaf(f, SCALE14, bs[g * 32 + j + t]);
            }
            *(float4*)(dst + g * 32 + j) = o;
        }
    }
    TCG_FENCE_BEFORE();
    __syncthreads();
    if (wid == 0) TCG_DEALLOC(tb, 512);
    if (tid == 0) atomicAdd(&g_tc_done, 1);
    CLUSTER_SYNC();                            // no exit while peer MC in flight
#endif // SNN_HAS_TCG
}

// ---------------------------------------------------------------------------
// Fallback: R1-proven fp32 FFMA GEMM (folds to early-return when tc ran).
// ---------------------------------------------------------------------------
__global__ __launch_bounds__(256)
void fc1_ffma(const float* __restrict__ A,
              const float* __restrict__ W,
              const float* __restrict__ bias)
{
    if (g_tc_done == TC_CTAS) return;

    const int K = SNN_NI;
    __shared__ float As[16][128];
    __shared__ float Ws[16][128];

    const int tid  = threadIdx.x;
    const int bn   = blockIdx.x;
    const int bm   = blockIdx.y;
    const int lrow = tid >> 2;
    const int lc4  = (tid & 3) << 2;
    const int tx   = tid & 15;
    const int ty   = tid >> 4;

    const float* Ab = A + (size_t)bm * 128 * K;
    const float* Wb = W + (size_t)bn * 128 * K;

    float acc[8][8];
#pragma unroll
    for (int i = 0; i < 8; i++)
#pragma unroll
        for (int j = 0; j < 8; j++) acc[i][j] = 0.f;

    for (int k0 = 0; k0 < K; k0 += 16) {
        float4 a0 = *(const float4*)(Ab + (size_t)lrow        * K + k0 + lc4);
        float4 a1 = *(const float4*)(Ab + (size_t)(lrow + 64) * K + k0 + lc4);
        float4 w0 = *(const float4*)(Wb + (size_t)lrow        * K + k0 + lc4);
        float4 w1 = *(const float4*)(Wb + (size_t)(lrow + 64) * K + k0 + lc4);

        __syncthreads();
        As[lc4 + 0][lrow]      = a0.x;
        As[lc4 + 1][lrow]      = a0.y;
        As[lc4 + 2][lrow]      = a0.z;
        As[lc4 + 3][lrow]      = a0.w;
        As[lc4 + 0][lrow + 64] = a1.x;
        As[lc4 + 1][lrow + 64] = a1.y;
        As[lc4 + 2][lrow + 64] = a1.z;
        As[lc4 + 3][lrow + 64] = a1.w;
        Ws[lc4 + 0][lrow]      = w0.x;
        Ws[lc4 + 1][lrow]      = w0.y;
        Ws[lc4 + 2][lrow]      = w0.z;
        Ws[lc4 + 3][lrow]      = w0.w;
        Ws[lc4 + 0][lrow + 64] = w1.x;
        Ws[lc4 + 1][lrow + 64] = w1.y;
        Ws[lc4 + 2][lrow + 64] = w1.z;
        Ws[lc4 + 3][lrow + 64] = w1.w;
        __syncthreads();

#pragma unroll
        for (int kk = 0; kk < 16; kk++) {
            float ar[8], br[8];
            *(float4*)(ar)     = *(const float4*)&As[kk][ty * 8];
            *(float4*)(ar + 4) = *(const float4*)&As[kk][ty * 8 + 4];
            *(float4*)(br)     = *(const float4*)&Ws[kk][tx * 8];
            *(float4*)(br + 4) = *(const float4*)&Ws[kk][tx * 8 + 4];
#pragma unroll
            for (int i = 0; i < 8; i++)
#pragma unroll
                for (int j = 0; j < 8; j++)
                    acc[i][j] = fmaf(ar[i], br[j], acc[i][j]);
        }
    }

    const int n0 = bn * 128 + tx * 8;
    const int m0 = bm * 128 + ty * 8;
    float bv[8];
#pragma unroll
    for (int j = 0; j < 8; j++) bv[j] = bias[n0 + j];

#pragma unroll
    for (int i = 0; i < 8; i++) {
        float4 o0, o1;
        o0.x = acc[i][0] + bv[0];
        o0.y = acc[i][1] + bv[1];
        o0.z = acc[i][2] + bv[2];
        o0.w = acc[i][3] + bv[3];
        o1.x = acc[i][4] + bv[4];
        o1.y = acc[i][5] + bv[5];
        o1.z = acc[i][6] + bv[6];
        o1.w = acc[i][7] + bv[7];
        float* Crow = g_cur1 + (size_t)(m0 + i) * SNN_NH + n0;
        *(float4*)(Crow)     = o0;
        *(float4*)(Crow + 4) = o1;
    }
}

// ---------------------------------------------------------------------------
// sequential SNN scan (R1-proven)
// ---------------------------------------------------------------------------
__global__ __launch_bounds__(1024)
void snn_scan(const float* __restrict__ w2, const float* __restrict__ b2,
              float* __restrict__ out_mem, float* __restrict__ out_spk) {
    const int b = blockIdx.x;
    const int h = threadIdx.x;
    const float ALPHA = 0.8187307530779818f;
    const float BETA  = 0.9048374180359595f;

    __shared__ float red0[32];
    __shared__ float red1[32];

    const float w20 = w2[h];
    const float w21 = w2[SNN_NH + h];
    const float b20 = b2[0];
    const float b21 = b2[1];

    float syn1 = 0.f, mem1 = 0.f;
    float syn2a = 0.f, mem2a = 0.f, syn2b = 0.f, mem2b = 0.f;

    const float* cp = g_cur1 + (size_t)b * SNN_T * SNN_NH + h;
    float cur_next = cp[0];

    const int lane = h & 31;
    const int warp = h >> 5;

    for (int t = 0; t < SNN_T; t++) {
        float cur = cur_next;
        if (t + 1 < SNN_T) cur_next = cp[(size_t)(t + 1) * SNN_NH];

        float r1 = (mem1 > 1.0f) ? 1.0f : 0.0f;
        syn1 = fmaf(ALPHA, syn1, cur);
        mem1 = fmaf(BETA, mem1, syn1) - r1;
        float spk = (mem1 > 1.0f) ? 1.0f : 0.0f;

        float v0 = spk * w20;
        float v1 = spk * w21;
#pragma unroll
        for (int off = 16; off > 0; off >>= 1) {
            v0 += __shfl_down_sync(0xffffffffu, v0, off);
            v1 += __shfl_down_sync(0xffffffffu, v1, off);
        }
        if (lane == 0) { red0[warp] = v0; red1[warp] = v1; }
        __syncthreads();

        if (h < 32) {
            float s0 = red0[h];
            float s1 = red1[h];
#pragma unroll
            for (int off = 16; off > 0; off >>= 1) {
                s0 += __shfl_down_sync(0xffffffffu, s0, off);
                s1 += __shfl_down_sync(0xffffffffu, s1, off);
            }
            if (h == 0) {
                float c0 = s0 + b20;
                float c1 = s1 + b21;
                float r2a = (mem2a > 1.0f) ? 1.0f : 0.0f;
                float r2b = (mem2b > 1.0f) ? 1.0f : 0.0f;
                syn2a = fmaf(ALPHA, syn2a, c0);
                syn2b = fmaf(ALPHA, syn2b, c1);
                mem2a = fmaf(BETA, mem2a, syn2a) - r2a;
                mem2b = fmaf(BETA, mem2b, syn2b) - r2b;
                size_t o = ((size_t)b * SNN_T + t) * 2;
                out_mem[o]     = mem2a;
                out_mem[o + 1] = mem2b;
                out_spk[o]     = (mem2a > 1.0f) ? 1.0f : 0.0f;
                out_spk[o + 1] = (mem2b > 1.0f) ? 1.0f : 0.0f;
            }
        }
        __syncthreads();
    }
}

// ---------------------------------------------------------------------------
// Launch
// ---------------------------------------------------------------------------
typedef CUresult (*PFN_tmap_encode)(
    CUtensorMap*, CUtensorMapDataType, cuuint32_t, void*,
    const cuuint64_t*, const cuuint64_t*, const cuuint32_t*, const cuuint32_t*,
    CUtensorMapInterleave, CUtensorMapSwizzle, CUtensorMapL2promotion,
    CUtensorMapFloatOOBfill);

extern "C" void kernel_launch(void* const* d_in, const int* in_sizes, int n_in,
                              void* d_out, int out_size) {
    const float* x  = (const float*)d_in[0];
    const float* w1 = (const float*)d_in[1];
    const float* b1 = (const float*)d_in[2];
    const float* w2 = (const float*)d_in[3];
    const float* b2 = (const float*)d_in[4];
    float* out = (float*)d_out;
    float* out_mem = out;
    float* out_spk = out + (size_t)SNN_B * SNN_T * SNN_NO;

    void* aPtr = nullptr;
    void* wPtr = nullptr;
    cudaGetSymbolAddress(&aPtr, g_Xi);
    cudaGetSymbolAddress(&wPtr, g_Wi);

    CUtensorMap tmA = {}, tmB = {};
    PFN_tmap_encode pfn = nullptr;
    cudaDriverEntryPointQueryResult qres;
    cudaGetDriverEntryPoint("cuTensorMapEncodeTiled", (void**)&pfn,
                            cudaEnableDefault, &qres);
    if (pfn && aPtr && wPtr) {
        cuuint64_t dimsA[2]   = {XI_W, SNN_M};
        cuuint64_t strideA[1] = {XI_W * 2};
        cuuint32_t box[2]     = {64, 128};
        cuuint32_t est[2]     = {1, 1};
        pfn(&tmA, CU_TENSOR_MAP_DATA_TYPE_BFLOAT16, 2, aPtr, dimsA, strideA,
            box, est, CU_TENSOR_MAP_INTERLEAVE_NONE, CU_TENSOR_MAP_SWIZZLE_128B,
            CU_TENSOR_MAP_L2_PROMOTION_L2_128B, CU_TENSOR_MAP_FLOAT_OOB_FILL_NONE);
        cuuint64_t dimsB[2]   = {XI_W, SNN_NH};
        cuuint64_t strideB[1] = {XI_W * 2};
        pfn(&tmB, CU_TENSOR_MAP_DATA_TYPE_BFLOAT16, 2, wPtr, dimsB, strideB,
            box, est, CU_TENSOR_MAP_INTERLEAVE_NONE, CU_TENSOR_MAP_SWIZZLE_128B,
            CU_TENSOR_MAP_L2_PROMOTION_L2_128B, CU_TENSOR_MAP_FLOAT_OOB_FILL_NONE);
    }

    cudaFuncSetAttribute(fc1_tc, cudaFuncAttributeMaxDynamicSharedMemorySize, T_SMEM);

    const int nx4 = SNN_M * SNN_NI / 4;
    const int nw4 = SNN_NH * SNN_NI / 4;
    quantX<<<(nx4 + 255) / 256, 256>>>((const float4*)x, nx4);
    quantW<<<(nw4 + 255) / 256, 256>>>((const float4*)w1, nw4);

    dim3 grid_tc(SNN_NH / 128, SNN_M / 128);   // (8, 200); cluster (2,1,1)
    fc1_tc<<<grid_tc, 128, T_SMEM>>>(tmA, tmB, b1);

    dim3 grid_ff(SNN_NH / 128, SNN_M / 128);
    fc1_ffma<<<grid_ff, 256>>>(x, w1, b1);

    snn_scan<<<SNN_B, 1024>>>(w2, b2, out_mem, out_spk);

    (void)in_sizes; (void)n_in; (void)out_size;
}